// round 2
// baseline (speedup 1.0000x reference)
#include <cuda_runtime.h>
#include <math.h>

// Problem constants
#define BATCH 4
#define NSEQ  2048
#define DIMX  512
#define HEADS 8
#define DHEAD 64
#define M_ROWS (BATCH * NSEQ)      // 8192
#define N_QKV  (3 * DIMX)          // 1536
#define ATT_SCALE 0.125f           // 64^-0.5

// Scratch (device globals; no runtime allocation allowed)
__device__ float g_Q[BATCH * HEADS * NSEQ * DHEAD];  // [bh][n][64], pre-scaled
__device__ float g_K[BATCH * HEADS * NSEQ * DHEAD];
__device__ float g_V[BATCH * HEADS * NSEQ * DHEAD];
__device__ float g_O[M_ROWS * DIMX];                 // [b*n][h*64+dh]

// ---------------------------------------------------------------------------
// Kernel 1: QKV GEMM  (A = x [8192,512], B = w_qkv [512,1536])
// 128x128 tile, BK=8, 256 threads, 8x8 per thread.
// Epilogue scatters into head-major Q/K/V, folding ATT_SCALE into Q.
// ---------------------------------------------------------------------------
__global__ __launch_bounds__(256) void qkv_gemm_kernel(
    const float* __restrict__ A, const float* __restrict__ B)
{
    __shared__ float As[8][128];
    __shared__ float Bs[8][128];

    const int tid = threadIdx.x;
    const int m0 = blockIdx.y * 128;
    const int n0 = blockIdx.x * 128;
    const int tx = tid & 15;
    const int ty = tid >> 4;

    const int a_row = tid >> 1;          // 0..127
    const int a_col = (tid & 1) * 4;     // 0 or 4
    const int b_row = tid >> 5;          // 0..7
    const int b_col = (tid & 31) * 4;    // 0..124

    float acc[8][8];
#pragma unroll
    for (int i = 0; i < 8; i++)
#pragma unroll
        for (int j = 0; j < 8; j++) acc[i][j] = 0.0f;

    for (int k0 = 0; k0 < DIMX; k0 += 8) {
        float4 av = *(const float4*)&A[(size_t)(m0 + a_row) * DIMX + k0 + a_col];
        As[a_col + 0][a_row] = av.x;
        As[a_col + 1][a_row] = av.y;
        As[a_col + 2][a_row] = av.z;
        As[a_col + 3][a_row] = av.w;
        float4 bv = *(const float4*)&B[(size_t)(k0 + b_row) * N_QKV + n0 + b_col];
        *(float4*)&Bs[b_row][b_col] = bv;
        __syncthreads();

#pragma unroll
        for (int k = 0; k < 8; k++) {
            float ar[8], br[8];
            float4 t0 = *(const float4*)&As[k][ty * 8];
            float4 t1 = *(const float4*)&As[k][ty * 8 + 4];
            ar[0]=t0.x; ar[1]=t0.y; ar[2]=t0.z; ar[3]=t0.w;
            ar[4]=t1.x; ar[5]=t1.y; ar[6]=t1.z; ar[7]=t1.w;
            float4 u0 = *(const float4*)&Bs[k][tx * 8];
            float4 u1 = *(const float4*)&Bs[k][tx * 8 + 4];
            br[0]=u0.x; br[1]=u0.y; br[2]=u0.z; br[3]=u0.w;
            br[4]=u1.x; br[5]=u1.y; br[6]=u1.z; br[7]=u1.w;
#pragma unroll
            for (int i = 0; i < 8; i++)
#pragma unroll
                for (int j = 0; j < 8; j++)
                    acc[i][j] = fmaf(ar[i], br[j], acc[i][j]);
        }
        __syncthreads();
    }

    // Epilogue: scatter into head-major layout.
    // col = n0 + tx*8 + j. A group of 8 cols never crosses a head (64) or
    // section (512) boundary since tiles are 8-aligned.
    const int col_base = n0 + tx * 8;
    const int sec = col_base >> 9;            // 0=Q,1=K,2=V
    const int inner = col_base & 511;
    const int h = inner >> 6;
    const int dh = inner & 63;
    float* dst = (sec == 0) ? g_Q : (sec == 1) ? g_K : g_V;
    const float mul = (sec == 0) ? ATT_SCALE : 1.0f;

#pragma unroll
    for (int i = 0; i < 8; i++) {
        int m = m0 + ty * 8 + i;
        int b = m >> 11;          // /2048
        int n = m & 2047;
        size_t base = ((size_t)((b << 3) + h) * NSEQ + n) * DHEAD + dh;
        float4 v0, v1;
        v0.x = acc[i][0] * mul; v0.y = acc[i][1] * mul;
        v0.z = acc[i][2] * mul; v0.w = acc[i][3] * mul;
        v1.x = acc[i][4] * mul; v1.y = acc[i][5] * mul;
        v1.z = acc[i][6] * mul; v1.w = acc[i][7] * mul;
        *(float4*)&dst[base]     = v0;
        *(float4*)&dst[base + 4] = v1;
    }
}

// ---------------------------------------------------------------------------
// Kernel 2: flash attention (fp32).
// Grid: (32 q-tiles, 32 bh). Block 256 threads = 16x16.
// Tile: 64 queries x 64 keys, d=64. Online softmax.
// Row pitch 68 floats keeps 16B alignment (68*4 = 272 = 17*16).
// ---------------------------------------------------------------------------
#define PITCH 68
#define ATT_SMEM_FLOATS (4 * 64 * PITCH)   // Qs,Ks,Vs,Ps
#define ATT_SMEM_BYTES  (ATT_SMEM_FLOATS * 4)

__global__ __launch_bounds__(256) void attn_kernel()
{
    extern __shared__ float sm[];
    float* Qs = sm;                   // [64][PITCH]  (row, d)
    float* Ks = sm + 64 * PITCH;      // [64][PITCH]  (key, d)
    float* Vs = sm + 2 * 64 * PITCH;  // [64][PITCH]  (key, dv)
    float* Ps = sm + 3 * 64 * PITCH;  // [64][PITCH]  TRANSPOSED: (key, row)

    const int tid = threadIdx.x;
    const int tx = tid & 15;
    const int ty = tid >> 4;
    const int r0 = ty * 4;
    const int c0 = tx * 4;

    const int bh = blockIdx.y;
    const int q0 = blockIdx.x * 64;
    const float* Qg = g_Q + (size_t)bh * NSEQ * DHEAD;
    const float* Kg = g_K + (size_t)bh * NSEQ * DHEAD;
    const float* Vg = g_V + (size_t)bh * NSEQ * DHEAD;

    // Load Q tile
    for (int i = tid; i < 1024; i += 256) {
        int r = i >> 4;
        int c = (i & 15) * 4;
        *(float4*)&Qs[r * PITCH + c] = *(const float4*)&Qg[(size_t)(q0 + r) * DHEAD + c];
    }

    float m_i[4], l_i[4], o[4][4];
#pragma unroll
    for (int i = 0; i < 4; i++) {
        m_i[i] = -INFINITY;
        l_i[i] = 0.0f;
#pragma unroll
        for (int j = 0; j < 4; j++) o[i][j] = 0.0f;
    }

    for (int kt = 0; kt < NSEQ / 64; kt++) {
        __syncthreads();   // previous iteration done with Ks/Vs/Ps
        const int k0 = kt * 64;
        for (int i = tid; i < 1024; i += 256) {
            int r = i >> 4;
            int c = (i & 15) * 4;
            *(float4*)&Ks[r * PITCH + c] = *(const float4*)&Kg[(size_t)(k0 + r) * DHEAD + c];
            *(float4*)&Vs[r * PITCH + c] = *(const float4*)&Vg[(size_t)(k0 + r) * DHEAD + c];
        }
        __syncthreads();

        // S = Q K^T  (4x4 per thread)
        float s[4][4];
#pragma unroll
        for (int i = 0; i < 4; i++)
#pragma unroll
            for (int j = 0; j < 4; j++) s[i][j] = 0.0f;

        for (int d = 0; d < DHEAD; d += 4) {
            float4 q[4], k[4];
#pragma unroll
            for (int i = 0; i < 4; i++) q[i] = *(const float4*)&Qs[(r0 + i) * PITCH + d];
#pragma unroll
            for (int j = 0; j < 4; j++) k[j] = *(const float4*)&Ks[(c0 + j) * PITCH + d];
#pragma unroll
            for (int i = 0; i < 4; i++)
#pragma unroll
                for (int j = 0; j < 4; j++) {
                    s[i][j] = fmaf(q[i].x, k[j].x, s[i][j]);
                    s[i][j] = fmaf(q[i].y, k[j].y, s[i][j]);
                    s[i][j] = fmaf(q[i].z, k[j].z, s[i][j]);
                    s[i][j] = fmaf(q[i].w, k[j].w, s[i][j]);
                }
        }

        // Row max over 64 keys: local over 4 j, then across 16 lanes (same ty)
        float mt[4], rs[4];
#pragma unroll
        for (int i = 0; i < 4; i++) {
            float m = fmaxf(fmaxf(s[i][0], s[i][1]), fmaxf(s[i][2], s[i][3]));
#pragma unroll
            for (int off = 8; off > 0; off >>= 1)
                m = fmaxf(m, __shfl_xor_sync(0xffffffffu, m, off));
            mt[i] = m;
        }

        float corr[4];
#pragma unroll
        for (int i = 0; i < 4; i++) {
            float m_new = fmaxf(m_i[i], mt[i]);
            corr[i] = __expf(m_i[i] - m_new);
            m_i[i] = m_new;
            float r = 0.0f;
#pragma unroll
            for (int j = 0; j < 4; j++) {
                s[i][j] = __expf(s[i][j] - m_new);
                r += s[i][j];
            }
#pragma unroll
            for (int off = 8; off > 0; off >>= 1)
                r += __shfl_xor_sync(0xffffffffu, r, off);
            rs[i] = r;
            l_i[i] = l_i[i] * corr[i] + rs[i];
#pragma unroll
            for (int j = 0; j < 4; j++) o[i][j] *= corr[i];
        }

        // Stage P transposed: Ps[key][row]
#pragma unroll
        for (int j = 0; j < 4; j++)
#pragma unroll
            for (int i = 0; i < 4; i++)
                Ps[(c0 + j) * PITCH + (r0 + i)] = s[i][j];
        __syncthreads();

        // O += P V
        for (int jk = 0; jk < 64; jk++) {
            float4 pv = *(const float4*)&Ps[jk * PITCH + r0];
            float4 vv = *(const float4*)&Vs[jk * PITCH + c0];
            float pr[4] = {pv.x, pv.y, pv.z, pv.w};
            float vc[4] = {vv.x, vv.y, vv.z, vv.w};
#pragma unroll
            for (int i = 0; i < 4; i++)
#pragma unroll
                for (int j = 0; j < 4; j++)
                    o[i][j] = fmaf(pr[i], vc[j], o[i][j]);
        }
    }

    // Normalize and write to g_O in [b*n][h*64+dh] layout
    const int b = bh >> 3;
    const int h = bh & 7;
#pragma unroll
    for (int i = 0; i < 4; i++) {
        float inv = 1.0f / l_i[i];
        int n = q0 + r0 + i;
        size_t base = ((size_t)(b * NSEQ + n)) * DIMX + h * DHEAD + c0;
        float4 v;
        v.x = o[i][0] * inv; v.y = o[i][1] * inv;
        v.z = o[i][2] * inv; v.w = o[i][3] * inv;
        *(float4*)&g_O[base] = v;
    }
}

// ---------------------------------------------------------------------------
// Kernel 3: output projection  (A = g_O [8192,512], B = w_out [512,512]) + bias
// ---------------------------------------------------------------------------
__global__ __launch_bounds__(256) void out_gemm_kernel(
    const float* __restrict__ B, const float* __restrict__ bias,
    float* __restrict__ out)
{
    __shared__ float As[8][128];
    __shared__ float Bs[8][128];

    const int tid = threadIdx.x;
    const int m0 = blockIdx.y * 128;
    const int n0 = blockIdx.x * 128;
    const int tx = tid & 15;
    const int ty = tid >> 4;

    const int a_row = tid >> 1;
    const int a_col = (tid & 1) * 4;
    const int b_row = tid >> 5;
    const int b_col = (tid & 31) * 4;

    float acc[8][8];
#pragma unroll
    for (int i = 0; i < 8; i++)
#pragma unroll
        for (int j = 0; j < 8; j++) acc[i][j] = 0.0f;

    const float* A = g_O;
    for (int k0 = 0; k0 < DIMX; k0 += 8) {
        float4 av = *(const float4*)&A[(size_t)(m0 + a_row) * DIMX + k0 + a_col];
        As[a_col + 0][a_row] = av.x;
        As[a_col + 1][a_row] = av.y;
        As[a_col + 2][a_row] = av.z;
        As[a_col + 3][a_row] = av.w;
        float4 bv = *(const float4*)&B[(size_t)(k0 + b_row) * DIMX + n0 + b_col];
        *(float4*)&Bs[b_row][b_col] = bv;
        __syncthreads();

#pragma unroll
        for (int k = 0; k < 8; k++) {
            float ar[8], br[8];
            float4 t0 = *(const float4*)&As[k][ty * 8];
            float4 t1 = *(const float4*)&As[k][ty * 8 + 4];
            ar[0]=t0.x; ar[1]=t0.y; ar[2]=t0.z; ar[3]=t0.w;
            ar[4]=t1.x; ar[5]=t1.y; ar[6]=t1.z; ar[7]=t1.w;
            float4 u0 = *(const float4*)&Bs[k][tx * 8];
            float4 u1 = *(const float4*)&Bs[k][tx * 8 + 4];
            br[0]=u0.x; br[1]=u0.y; br[2]=u0.z; br[3]=u0.w;
            br[4]=u1.x; br[5]=u1.y; br[6]=u1.z; br[7]=u1.w;
#pragma unroll
            for (int i = 0; i < 8; i++)
#pragma unroll
                for (int j = 0; j < 8; j++)
                    acc[i][j] = fmaf(ar[i], br[j], acc[i][j]);
        }
        __syncthreads();
    }

    const int col = n0 + tx * 8;
    float bb[8];
#pragma unroll
    for (int j = 0; j < 8; j++) bb[j] = bias[col + j];

#pragma unroll
    for (int i = 0; i < 8; i++) {
        int m = m0 + ty * 8 + i;
        float4 v0, v1;
        v0.x = acc[i][0] + bb[0]; v0.y = acc[i][1] + bb[1];
        v0.z = acc[i][2] + bb[2]; v0.w = acc[i][3] + bb[3];
        v1.x = acc[i][4] + bb[4]; v1.y = acc[i][5] + bb[5];
        v1.z = acc[i][6] + bb[6]; v1.w = acc[i][7] + bb[7];
        *(float4*)&out[(size_t)m * DIMX + col]     = v0;
        *(float4*)&out[(size_t)m * DIMX + col + 4] = v1;
    }
}

// ---------------------------------------------------------------------------
extern "C" void kernel_launch(void* const* d_in, const int* in_sizes, int n_in,
                              void* d_out, int out_size)
{
    const float* x     = (const float*)d_in[0];  // [4,2048,512]
    const float* w_qkv = (const float*)d_in[1];  // [512,1536]
    const float* w_out = (const float*)d_in[2];  // [512,512]
    const float* b_out = (const float*)d_in[3];  // [512]
    float* out = (float*)d_out;

    // Attention kernel uses ~68KB dynamic smem (attribute is sticky & idempotent)
    cudaFuncSetAttribute(attn_kernel,
                         cudaFuncAttributeMaxDynamicSharedMemorySize,
                         ATT_SMEM_BYTES);

    qkv_gemm_kernel<<<dim3(N_QKV / 128, M_ROWS / 128), 256>>>(x, w_qkv);
    attn_kernel<<<dim3(NSEQ / 64, BATCH * HEADS), 256, ATT_SMEM_BYTES>>>();
    out_gemm_kernel<<<dim3(DIMX / 128, M_ROWS / 128), 256>>>(w_out, b_out, out);
}